// round 3
// baseline (speedup 1.0000x reference)
#include <cuda_runtime.h>
#include <math.h>

// Shapes fixed by reference: [2,4,32,64,64]
constexpr int Cc   = 32;          // channels
constexpr int HW   = 4096;        // 64*64 positions
constexpr int NI   = 8;           // B*L items
constexpr int BPI  = 64;          // blocks per item
constexpr int TP   = 64;          // positions per block (one tile)
constexpr int PITCH = 66;         // even (8B rows for LDS.64), not mult of 4 (bank spread)
constexpr int TH1  = 192;         // 3 groups x 64 threads

// Scratch: [item][block][mat(A,B,M)][32*32]
__device__ float g_scr1[(size_t)NI * BPI * 3 * 1024];
__device__ float g_part[64];

__global__ __launch_bounds__(TH1) void k_partial(const float* __restrict__ S,
                                                 const float* __restrict__ T) {
    __shared__ float sS[Cc][PITCH];
    __shared__ float sT[Cc][PITCH];
    __shared__ float invS[TP], invT[TP];

    const int n   = blockIdx.y;
    const int blk = blockIdx.x;
    const int tid = threadIdx.x;
    const int p0  = blk * TP;

    const float2* __restrict__ Sb2 = (const float2*)(S + (size_t)n * Cc * HW);
    const float2* __restrict__ Tb2 = (const float2*)(T + (size_t)n * Cc * HW);

    // ---- Load tile [32 x 64] as float2 (coalesced; STS.64 conflict-free) ----
    for (int v = tid; v < Cc * (TP / 2); v += TH1) {
        const int c = v >> 5;          // channel
        const int q = v & 31;          // float2 index within row
        const float2 a = Sb2[((size_t)c * HW + p0) / 2 + q];
        const float2 b = Tb2[((size_t)c * HW + p0) / 2 + q];
        *(float2*)&sS[c][2 * q] = a;
        *(float2*)&sT[c][2 * q] = b;
    }
    __syncthreads();

    // ---- Per-position inverse norms (lanes read contiguous p: conflict-free) ----
    if (tid < TP) {
        float s = 0.f;
#pragma unroll
        for (int c = 0; c < Cc; ++c) { const float v = sS[c][tid]; s = fmaf(v, v, s); }
        invS[tid] = 1.f / (sqrtf(s) + 1e-8f);
    } else if (tid < 2 * TP) {
        const int p = tid - TP;
        float s = 0.f;
#pragma unroll
        for (int c = 0; c < Cc; ++c) { const float v = sT[c][p]; s = fmaf(v, v, s); }
        invT[p] = 1.f / (sqrtf(s) + 1e-8f);
    }
    __syncthreads();

    // ---- Normalize in place (float2) ----
    for (int v = tid; v < Cc * (TP / 2); v += TH1) {
        const int c = v >> 5;
        const int q = v & 31;
        const float2 is = *(const float2*)&invS[2 * q];
        const float2 it = *(const float2*)&invT[2 * q];
        float2 a = *(float2*)&sS[c][2 * q];
        float2 b = *(float2*)&sT[c][2 * q];
        a.x *= is.x; a.y *= is.y;
        b.x *= it.x; b.y *= it.y;
        *(float2*)&sS[c][2 * q] = a;
        *(float2*)&sT[c][2 * q] = b;
    }
    __syncthreads();

    // ---- Rank-2 accumulation: f32x2 over (even p, odd p) lanes ----
    // group 0 -> A (T.T^t), group 1 -> B (S.S^t), group 2 -> M (S.T^t)
    const int grp = tid >> 6;
    const int lt  = tid & 63;
    const int i0  = (lt >> 3) << 2;   // 0,4,...,28
    const int j0  = (lt & 7) << 2;    // 0,4,...,28

    const float (*Xi)[PITCH] = (grp == 0) ? sT : sS;
    const float (*Xj)[PITCH] = (grp == 1) ? sS : sT;

    unsigned long long acc2[16];
#pragma unroll
    for (int k = 0; k < 16; ++k) acc2[k] = 0ull;

#pragma unroll 4
    for (int p = 0; p < TP; p += 2) {
        unsigned long long xi2[4], xj2[4];
#pragma unroll
        for (int r = 0; r < 4; ++r)
            xi2[r] = *(const unsigned long long*)&Xi[i0 + r][p];
#pragma unroll
        for (int q = 0; q < 4; ++q)
            xj2[q] = *(const unsigned long long*)&Xj[j0 + q][p];
#pragma unroll
        for (int r = 0; r < 4; ++r)
#pragma unroll
            for (int q = 0; q < 4; ++q)
                asm("fma.rn.f32x2 %0, %1, %2, %0;"
                    : "+l"(acc2[r * 4 + q])
                    : "l"(xi2[r]), "l"(xj2[q]));
    }

    // ---- Horizontal add of the two p-lanes, write partials ----
    float* out = g_scr1 + (((size_t)n * BPI + blk) * 3 + grp) * 1024;
#pragma unroll
    for (int r = 0; r < 4; ++r)
#pragma unroll
        for (int q = 0; q < 4; ++q) {
            const float2 v = *(const float2*)&acc2[r * 4 + q];
            out[(i0 + r) * Cc + (j0 + q)] = v.x + v.y;
        }
}

// 64 blocks: (item n, slice s). Sum block partials per element, square, weight,
// block-reduce. 512 threads: 384 active (3 mats x 128-entry slice).
__global__ __launch_bounds__(512) void k_reduce1() {
    const int bid = blockIdx.x;
    const int n = bid >> 3;
    const int s = bid & 7;
    const int t = threadIdx.x;

    float contrib = 0.f;
    if (t < 384) {
        const int mat = t >> 7;          // 0,1,2
        const int e   = s * 128 + (t & 127);
        float v = 0.f;
#pragma unroll 8
        for (int b = 0; b < BPI; ++b)
            v += g_scr1[(((size_t)n * BPI + b) * 3 + mat) * 1024 + e];
        contrib = (mat == 2) ? -2.f * v * v : v * v;
    }

    __shared__ float red[512];
    red[t] = contrib;
    __syncthreads();
    for (int off = 256; off > 0; off >>= 1) {
        if (t < off) red[t] += red[t + off];
        __syncthreads();
    }
    if (t == 0) g_part[bid] = red[0];
}

__global__ __launch_bounds__(64) void k_reduce2(float* __restrict__ out) {
    const int t = threadIdx.x;
    __shared__ float red[64];
    red[t] = g_part[t];
    __syncthreads();
    for (int off = 32; off > 0; off >>= 1) {
        if (t < off) red[t] += red[t + off];
        __syncthreads();
    }
    // loss = total / (HW^2) / (B*L)
    if (t == 0) out[0] = red[0] * (1.f / (16777216.f * 8.f));
}

extern "C" void kernel_launch(void* const* d_in, const int* in_sizes, int n_in,
                              void* d_out, int out_size) {
    const float* S = (const float*)d_in[0];
    const float* T = (const float*)d_in[1];
    (void)in_sizes; (void)n_in; (void)out_size;

    dim3 g1(BPI, NI);
    k_partial<<<g1, TH1>>>(S, T);
    k_reduce1<<<64, 512>>>();
    k_reduce2<<<1, 64>>>((float*)d_out);
}